// round 14
// baseline (speedup 1.0000x reference)
#include <cuda_runtime.h>

// ---------------- problem constants ----------------
#define TWO_PI_D 6.283185307179586
#define C_M  ((float)(1.0/(TWO_PI_D*128.0)))   // 1/(2pi*s1), s1=128 ; also c_g
#define C_H  ((float)(1.0/(TWO_PI_D*96.0)))    // 1/(2pi*s2), s2=96
#define C_V  ((float)((1.0/(TWO_PI_D*96.0))*(1.0/(TWO_PI_D*128.0))))
#define C_M2 ((float)((1.0/(TWO_PI_D*128.0))*(1.0/(TWO_PI_D*128.0))))

#define NB 8      // batch
#define NP 512    // points per image
#define KK 64     // grid per axis
#define GG 4096   // KK*KK
#define MMM 100   // M

// ---------------- scratch (__device__ globals; no allocs allowed) ----------------
__device__ float  g_vraw[NB*GG];
__device__ int    g_minds[NB*MMM];
__device__ float  g_vM[NB*MMM];
// midpoint exp tables: s (or t) in 0..126, padded to 128
__device__ float  g_Ex192[NB][NP][128];   // exp(-(x-(4s+4))^2/192)
__device__ float  g_Ex128[NB][NP][128];   // exp(-(x-(4s+4))^2/128)
__device__ float  g_Ey192[NB][NP][128];
__device__ float  g_Ey128[NB][NP][128];
// pair tables T[t][s], U[t][s]
__device__ float  g_T[NB][128][128];
__device__ float  g_U[NB][128][128];

// =====================================================================
// L1: blocks 0..63 compute v (8 iy-rows per block; per-cell accumulation
// chain over n bitwise-identical to prior rounds);
// blocks 64..4159: midpoint exp tables per (b, n)  (A path, __expf ok).
// =====================================================================
__global__ void k_v_emid(const float* __restrict__ pts,
                         float* __restrict__ out_v)
{
    int tid = threadIdx.x;
    if (blockIdx.x >= 64) {
        int u = blockIdx.x - 64;            // 0..4095
        int b = u >> 9, n = u & 511;
        float x = pts[2*u], y = pts[2*u + 1];
        if (tid < 128) {
            int s = tid;
            if (s < 127) {
                float d = x - (4.0f*(float)s + 4.0f);
                float d2 = d * d;
                g_Ex192[b][n][s] = __expf(-d2 * (1.0f/192.0f));
                g_Ex128[b][n][s] = __expf(-d2 * (1.0f/128.0f));
            } else {
                g_Ex192[b][n][127] = 0.0f;
                g_Ex128[b][n][127] = 0.0f;
            }
        } else {
            int s = tid - 128;
            if (s < 127) {
                float d = y - (4.0f*(float)s + 4.0f);
                float d2 = d * d;
                g_Ey192[b][n][s] = __expf(-d2 * (1.0f/192.0f));
                g_Ey128[b][n][s] = __expf(-d2 * (1.0f/128.0f));
            } else if (s == 127) {
                g_Ey192[b][n][127] = 0.0f;
                g_Ey128[b][n][127] = 0.0f;
            }
        }
        return;
    }
    // ---- v part: 8 blocks per batch, 8 iy-rows each, 2 cells/thread ----
    int b = blockIdx.x >> 3;
    int iy0 = (blockIdx.x & 7) << 3;
    __shared__ float sEx2[32][64], sEx1q[32][64];
    __shared__ float sEy2[32][8], sEy1q[32][8];
    int ix2 = (tid & 31) << 1;           // 2 consecutive ix per thread
    int iyl = tid >> 5;                  // 1 iy per thread (0..7)
    float accv[2], accm[2];
    accv[0] = accv[1] = accm[0] = accm[1] = 0.f;

    for (int c = 0; c < 16; c++) {
        __syncthreads();
        for (int idx = tid; idx < 2048; idx += 256) {
            int nl = idx >> 6, j = idx & 63;
            int n = (c << 5) + nl;
            float x = pts[(((b << 9) + n) << 1) + 0];
            float cd = 8.0f * (float)j + 4.0f;
            float dx = x - cd;
            float d2x = dx * dx;
            float e1x = expf(-d2x * (1.0f/256.0f));
            sEx1q[nl][j] = e1x * e1x;
            sEx2[nl][j]  = expf(-d2x * (1.0f/192.0f));
        }
        if (tid < 256) {
            int nl = tid >> 3, jl = tid & 7;
            int n = (c << 5) + nl;
            int j = iy0 + jl;
            float y = pts[(((b << 9) + n) << 1) + 1];
            float cd = 8.0f * (float)j + 4.0f;
            float dy = y - cd;
            float d2y = dy * dy;
            float e1y = expf(-d2y * (1.0f/256.0f));
            sEy1q[nl][jl] = e1y * e1y;
            sEy2[nl][jl]  = expf(-d2y * (1.0f/192.0f));
        }
        __syncthreads();
#pragma unroll 4
        for (int nl = 0; nl < 32; nl++) {
            float2 ex2 = *(const float2*)&sEx2[nl][ix2];
            float2 ex1 = *(const float2*)&sEx1q[nl][ix2];
            float ey2 = sEy2[nl][iyl];
            float ey1 = sEy1q[nl][iyl];
            accv[0] += ey2 * ex2.x;  accm[0] += ey1 * ex1.x;
            accv[1] += ey2 * ex2.y;  accm[1] += ey1 * ex1.y;
        }
    }
#pragma unroll
    for (int q = 0; q < 2; q++) {
        int g = (iy0 + iyl) * 64 + ix2 + q;
        float v = C_V * accv[q] - C_M2 * accm[q];
        g_vraw[b*GG + g] = v;
        out_v[b*GG + g]  = fmaxf(v, 1e-6f);
    }
}

// =====================================================================
// L2: heterogeneous launch.
//   blocks 0..7       : top-100 selection (stable argsort(-v))
//   blocks 8..135     : T/U table reductions (16 per batch, 8 t-rows each)
//   blocks 136..4231  : m = C_M*Ey1*Ex1  (HBM-bound write)
// =====================================================================
__device__ __forceinline__ unsigned int fordu(float f)
{
    unsigned int u = __float_as_uint(f);
    return (u & 0x80000000u) ? ~u : (u | 0x80000000u);
}

union SmemL2 {
    struct { unsigned long long keys[4096]; unsigned int top[128]; } s;
    struct { float tx[32][128], ux[32][128]; float ty[32][8], uy[32][8]; } t;
    struct { float ex[64], ey[64]; } m;
};

__global__ void k_sort_tab_m(const float* __restrict__ pts,
                             float* __restrict__ out_minds,
                             float* __restrict__ out_m)
{
    __shared__ SmemL2 u;
    int tid = threadIdx.x;
    int bx = blockIdx.x;

    if (bx >= 136) {
        // ---- m part ----
        int bn = bx - 136;
        float x = pts[2*bn], y = pts[2*bn + 1];
        if (tid < 64) {
            float cd = 8.0f * (float)tid + 4.0f;
            float dx = x - cd;
            u.m.ex[tid] = expf(-dx*dx * (1.0f/256.0f));
        } else if (tid < 128) {
            int j = tid - 64;
            float cd = 8.0f * (float)j + 4.0f;
            float dy = y - cd;
            u.m.ey[j] = expf(-dy*dy * (1.0f/256.0f));
        }
        __syncthreads();
        float4* mrow = (float4*)(out_m + (size_t)bn * GG);
        for (int i = tid; i < 1024; i += 256) {
            int g0 = i << 2;
            int iy = g0 >> 6, ix = g0 & 63;
            float e = C_M * u.m.ey[iy];
            mrow[i] = make_float4(e*u.m.ex[ix], e*u.m.ex[ix+1], e*u.m.ex[ix+2], e*u.m.ex[ix+3]);
        }
        return;
    }
    if (bx >= 8) {
        // ---- T/U table part: T[t][s] = sum_n Ey192[t]*Ex192[s]; U likewise ----
        int u2 = bx - 8;
        int b = u2 >> 4;
        int t00 = (u2 & 15) << 3;            // 8 t-rows per block
        int ox = (tid & 31) << 2;            // 4 s per thread
        int oyp = tid >> 5;                  // active threads: 0..3 (2 rows each)
        bool act = (tid < 128);
        float accT[2][4], accU[2][4];
#pragma unroll
        for (int r = 0; r < 2; r++)
#pragma unroll
            for (int q = 0; q < 4; q++) { accT[r][q] = 0.f; accU[r][q] = 0.f; }

        for (int c = 0; c < 16; c++) {
            int n0 = c << 5;
            __syncthreads();
            const float4* px = (const float4*)&g_Ex192[b][n0][0];
            const float4* pu = (const float4*)&g_Ex128[b][n0][0];
            for (int idx = tid; idx < 1024; idx += 256) {
                ((float4*)u.t.tx)[idx] = px[idx];
                ((float4*)u.t.ux)[idx] = pu[idx];
            }
            {
                int idx = tid;
                if (idx < 256) {
                    int nl = idx >> 3, yy = idx & 7;
                    u.t.ty[nl][yy] = g_Ey192[b][n0 + nl][t00 + yy];
                    u.t.uy[nl][yy] = g_Ey128[b][n0 + nl][t00 + yy];
                }
            }
            __syncthreads();
            if (act) {
#pragma unroll 4
                for (int nl = 0; nl < 32; nl++) {
                    float4 tx = *(const float4*)&u.t.tx[nl][ox];
                    float4 ux = *(const float4*)&u.t.ux[nl][ox];
                    float ty0 = u.t.ty[nl][2*oyp], ty1 = u.t.ty[nl][2*oyp+1];
                    float uy0 = u.t.uy[nl][2*oyp], uy1 = u.t.uy[nl][2*oyp+1];
                    accT[0][0] += ty0*tx.x; accT[0][1] += ty0*tx.y; accT[0][2] += ty0*tx.z; accT[0][3] += ty0*tx.w;
                    accT[1][0] += ty1*tx.x; accT[1][1] += ty1*tx.y; accT[1][2] += ty1*tx.z; accT[1][3] += ty1*tx.w;
                    accU[0][0] += uy0*ux.x; accU[0][1] += uy0*ux.y; accU[0][2] += uy0*ux.z; accU[0][3] += uy0*ux.w;
                    accU[1][0] += uy1*ux.x; accU[1][1] += uy1*ux.y; accU[1][2] += uy1*ux.z; accU[1][3] += uy1*ux.w;
                }
            }
        }
        if (act) {
#pragma unroll
            for (int r = 0; r < 2; r++) {
                int t = t00 + 2*oyp + r;
                *(float4*)&g_T[b][t][ox] = make_float4(accT[r][0], accT[r][1], accT[r][2], accT[r][3]);
                *(float4*)&g_U[b][t][ox] = make_float4(accU[r][0], accU[r][1], accU[r][2], accU[r][3]);
            }
        }
        return;
    }
    // ---- sort part ----
    int b = bx;
    for (int i = tid; i < 4096; i += 256) {
        float v = g_vraw[b*GG + i];
        u.s.keys[i] = ((unsigned long long)(~fordu(v)) << 32) | (unsigned int)i;
    }
    for (int k = 2; k <= 4096; k <<= 1)
        for (int j = k >> 1; j > 0; j >>= 1) {
            __syncthreads();
            for (int i = tid; i < 4096; i += 256) {
                int ixj = i ^ j;
                if (ixj > i) {
                    unsigned long long a = u.s.keys[i], c = u.s.keys[ixj];
                    bool up = ((i & k) == 0);
                    if ((a > c) == up) { u.s.keys[i] = c; u.s.keys[ixj] = a; }
                }
            }
        }
    __syncthreads();
    if (tid < 128)
        u.s.top[tid] = (tid < 100) ? (unsigned int)(u.s.keys[tid] & 0xFFFFFFFFu) : 0xFFFFFFFFu;
    for (int k = 2; k <= 128; k <<= 1)
        for (int j = k >> 1; j > 0; j >>= 1) {
            __syncthreads();
            if (tid < 128) {
                int i = tid, ixj = i ^ j;
                if (ixj > i) {
                    unsigned int a = u.s.top[i], c = u.s.top[ixj];
                    bool up = ((i & k) == 0);
                    if ((a > c) == up) { u.s.top[i] = c; u.s.top[ixj] = a; }
                }
            }
        }
    __syncthreads();
    if (tid < 100) {
        int mind = (int)u.s.top[tid];
        g_minds[b*MMM + tid] = mind;
        out_minds[b*MMM + tid] = (float)mind;
        float vr = g_vraw[b*GG + mind];
        g_vM[b*MMM + tid] = fmaxf(vr, 1e-6f) + 1e-10f;
    }
}

// =====================================================================
// L3 (fused): A assembly from tables + register-resident fp32
// Gauss-Jordan with partial pivoting.  ALL register-array accesses use
// STATIC indices (predicated unrolled loops) — no local-memory demotion.
//   E = A + diag(vM);  Bm = diag(1/vM) - inv(E)  (column-permuted gather).
// =====================================================================
__global__ void __launch_bounds__(512, 1) k_Ainv(float* __restrict__ out_A,
                                                 float* __restrict__ out_Bm)
{
    __shared__ float colA[104], colB[104];
    __shared__ float tmpK[104], rowk[104];
    __shared__ float svm[100];
    __shared__ int six[100], siy[100];
    __shared__ int piv[100], cperm[104], invp[104];
    __shared__ int s_pr;
    __shared__ float s_pinv;

    int b = blockIdx.x, tid = threadIdx.x;
    if (tid < 100) {
        svm[tid] = g_vM[b*MMM + tid];
        int mind = g_minds[b*MMM + tid];
        six[tid] = mind & 63;
        siy[tid] = mind >> 6;
    }
    __syncthreads();

    int jj = tid % 100;
    int rg = tid / 100;
    bool act = (tid < 500);

    // ---- build A (write out) and E = A + diag(vM) into registers ----
    float r[20];
    if (act) {
        int ixj = six[jj], iyj = siy[jj];
#pragma unroll
        for (int t = 0; t < 20; t++) {
            int rr = rg + 5*t;
            int ixi = six[rr], iyi = siy[rr];
            float Aij;
            if (rr == jj) {
                Aij = 1e-10f;
            } else {
                int s = ixi + ixj, tt = iyi + iyj;
                float Tv = g_T[b][tt][s];
                float Uv = g_U[b][tt][s];
                int dix = ixi - ixj, diy = iyi - iyj;
                float d2 = (float)(dix*dix + diy*diy);
                float e1 = __expf(-0.25f  * d2);
                float e2 = __expf(-0.125f * d2);
                Aij = C_M * e1 * (C_H * Tv + 512.0f) - C_M2 * e2 * Uv;
            }
            out_A[b*10000 + rr*100 + jj] = Aij;
            r[t] = Aij + ((rr == jj) ? svm[rr] : 0.0f);
        }
        if (jj == 0) {
#pragma unroll
            for (int t = 0; t < 20; t++) colA[rg + 5*t] = r[t];
        }
    }
    __syncthreads();

    // ---- Gauss-Jordan, 100 steps ----
    for (int k = 0; k < 100; k++) {
        float* colcur = (k & 1) ? colB : colA;
        float* colnxt = (k & 1) ? colA : colB;
        // Phase A: warp 0 pivot search on column k, rows [k,100)
        if (tid < 32) {
            float bv = -1.0f; int br = 0x7FFFFFFF;
#pragma unroll
            for (int q = 0; q < 4; q++) {
                int rr2 = k + tid + (q << 5);
                if (rr2 < 100) {
                    float av = fabsf(colcur[rr2]);
                    if (av > bv) { bv = av; br = rr2; }
                }
            }
#pragma unroll
            for (int off = 16; off; off >>= 1) {
                float ov = __shfl_down_sync(0xFFFFFFFFu, bv, off);
                int   oi = __shfl_down_sync(0xFFFFFFFFu, br, off);
                if (ov > bv || (ov == bv && oi < br)) { bv = ov; br = oi; }
            }
            if (tid == 0) {
                s_pr = br; piv[k] = br;
                s_pinv = 1.0f / colcur[br];
            }
        }
        __syncthreads();
        int pr = s_pr;
        float pinv = s_pinv;
        // Phase B1: stage old row k; build scaled pivot row (STATIC indices)
        if (act) {
#pragma unroll
            for (int t = 0; t < 20; t++) {
                int rr = rg + 5*t;
                if (rr == k)  tmpK[jj] = r[t];
                if (rr == pr) rowk[jj] = (jj == k) ? pinv : r[t] * pinv;
            }
        }
        __syncthreads();
        // Phase B2 + C: install swapped rows, eliminate, stage column k+1
        if (act) {
            float rk = rowk[jj];
            float cbk = colcur[k];
            bool isk = (jj == k);
#pragma unroll
            for (int t = 0; t < 20; t++) {
                int rr = rg + 5*t;
                if (rr == k) r[t] = rowk[jj];                   // new row k = scaled pivot row
                else if (pr != k && rr == pr) r[t] = tmpK[jj];  // new row pr = old row k
                float c = colcur[rr];
                if (rr == pr) c = cbk;
                if (rr == k)  c = 0.0f;
                if (isk && rr != k) r[t] = 0.0f;                // zero-column trick
                r[t] -= c * rk;
            }
            if (jj == k + 1) {
#pragma unroll
                for (int t = 0; t < 20; t++) colnxt[rg + 5*t] = r[t];
            }
        }
        __syncthreads();
    }

    // ---- column permutation (reverse row swaps) and output ----
    if (tid == 0) {
        for (int j2 = 0; j2 < 100; j2++) cperm[j2] = j2;
        for (int k = 99; k >= 0; k--) {
            int pp = piv[k];
            int t = cperm[k]; cperm[k] = cperm[pp]; cperm[pp] = t;
        }
    }
    __syncthreads();
    if (tid < 100) invp[cperm[tid]] = tid;
    __syncthreads();
    if (act) {
        int jc = invp[jj];
#pragma unroll
        for (int t = 0; t < 20; t++) {
            int rr = rg + 5*t;
            float d = (rr == jc) ? (1.0f / svm[rr]) : 0.0f;
            out_Bm[b*10000 + rr*100 + jc] = d - r[t];
        }
    }
}

// =====================================================================
// launch
// =====================================================================
extern "C" void kernel_launch(void* const* d_in, const int* in_sizes, int n_in,
                              void* d_out, int out_size)
{
    const float* pts = (const float*)d_in[0];
    float* out       = (float*)d_out;
    float* out_m     = out;                                   // 8*512*4096
    float* out_v     = out_m + (size_t)NB*NP*GG;              // 8*4096
    float* out_A     = out_v + (size_t)NB*GG;                 // 8*100*100
    float* out_Bm    = out_A + (size_t)NB*MMM*MMM;            // 8*100*100
    float* out_minds = out_Bm + (size_t)NB*MMM*MMM;           // 8*100

    k_v_emid<<<64 + NB*NP, 256>>>(pts, out_v);
    k_sort_tab_m<<<8 + 128 + NB*NP, 256>>>(pts, out_minds, out_m);
    k_Ainv<<<NB, 512>>>(out_A, out_Bm);
}

// round 15
// speedup vs baseline: 1.4239x; 1.4239x over previous
#include <cuda_runtime.h>

// ---------------- problem constants ----------------
#define TWO_PI_D 6.283185307179586
#define C_M  ((float)(1.0/(TWO_PI_D*128.0)))   // 1/(2pi*s1), s1=128 ; also c_g
#define C_H  ((float)(1.0/(TWO_PI_D*96.0)))    // 1/(2pi*s2), s2=96
#define C_V  ((float)((1.0/(TWO_PI_D*96.0))*(1.0/(TWO_PI_D*128.0))))
#define C_M2 ((float)((1.0/(TWO_PI_D*128.0))*(1.0/(TWO_PI_D*128.0))))

#define NB 8      // batch
#define NP 512    // points per image
#define KK 64     // grid per axis
#define GG 4096   // KK*KK
#define MMM 100   // M

// ---------------- scratch (__device__ globals; no allocs allowed) ----------------
__device__ float  g_vraw[NB*GG];
__device__ int    g_minds[NB*MMM];
__device__ float  g_vM[NB*MMM];
// midpoint exp tables: s (or t) in 0..126, padded to 128
__device__ float  g_Ex192[NB][NP][128];   // exp(-(x-(4s+4))^2/192)
__device__ float  g_Ex128[NB][NP][128];   // exp(-(x-(4s+4))^2/128)
__device__ float  g_Ey192[NB][NP][128];
__device__ float  g_Ey128[NB][NP][128];
// pair tables T[t][s], U[t][s]
__device__ float  g_T[NB][128][128];
__device__ float  g_U[NB][128][128];

// =====================================================================
// L1: blocks 0..63 compute v (8 iy-rows per block; per-cell accumulation
// chain over n bitwise-identical to prior rounds);
// blocks 64..575: midpoint exp tables, 8 points per block (dense).
// =====================================================================
__global__ void k_v_emid(const float* __restrict__ pts,
                         float* __restrict__ out_v)
{
    int tid = threadIdx.x;
    if (blockIdx.x >= 64) {
        // ---- emid part: 8 (b,n) points per block, 32 lanes each ----
        int g = ((blockIdx.x - 64) << 3) + (tid >> 5);  // 0..4095
        int lane = tid & 31;
        int b = g >> 9, n = g & 511;
        float x = pts[2*g], y = pts[2*g + 1];
#pragma unroll
        for (int q = 0; q < 4; q++) {
            int s = lane + (q << 5);
            if (s < 127) {
                float cd = 4.0f * (float)s + 4.0f;
                float dx = x - cd;
                float d2x = dx * dx;
                g_Ex192[b][n][s] = __expf(-d2x * (1.0f/192.0f));
                g_Ex128[b][n][s] = __expf(-d2x * (1.0f/128.0f));
                float dy = y - cd;
                float d2y = dy * dy;
                g_Ey192[b][n][s] = __expf(-d2y * (1.0f/192.0f));
                g_Ey128[b][n][s] = __expf(-d2y * (1.0f/128.0f));
            } else {
                g_Ex192[b][n][127] = 0.0f;
                g_Ex128[b][n][127] = 0.0f;
                g_Ey192[b][n][127] = 0.0f;
                g_Ey128[b][n][127] = 0.0f;
            }
        }
        return;
    }
    // ---- v part: 8 blocks per batch, 8 iy-rows each, 2 cells/thread ----
    int b = blockIdx.x >> 3;
    int iy0 = (blockIdx.x & 7) << 3;
    __shared__ float sEx2[32][64], sEx1q[32][64];
    __shared__ float sEy2[32][8], sEy1q[32][8];
    int ix2 = (tid & 31) << 1;           // 2 consecutive ix per thread
    int iyl = tid >> 5;                  // 1 iy per thread (0..7)
    float accv[2], accm[2];
    accv[0] = accv[1] = accm[0] = accm[1] = 0.f;

    for (int c = 0; c < 16; c++) {
        __syncthreads();
        for (int idx = tid; idx < 2048; idx += 256) {
            int nl = idx >> 6, j = idx & 63;
            int n = (c << 5) + nl;
            float x = pts[(((b << 9) + n) << 1) + 0];
            float cd = 8.0f * (float)j + 4.0f;
            float dx = x - cd;
            float d2x = dx * dx;
            float e1x = expf(-d2x * (1.0f/256.0f));
            sEx1q[nl][j] = e1x * e1x;
            sEx2[nl][j]  = expf(-d2x * (1.0f/192.0f));
        }
        if (tid < 256) {
            int nl = tid >> 3, jl = tid & 7;
            int n = (c << 5) + nl;
            int j = iy0 + jl;
            float y = pts[(((b << 9) + n) << 1) + 1];
            float cd = 8.0f * (float)j + 4.0f;
            float dy = y - cd;
            float d2y = dy * dy;
            float e1y = expf(-d2y * (1.0f/256.0f));
            sEy1q[nl][jl] = e1y * e1y;
            sEy2[nl][jl]  = expf(-d2y * (1.0f/192.0f));
        }
        __syncthreads();
#pragma unroll 4
        for (int nl = 0; nl < 32; nl++) {
            float2 ex2 = *(const float2*)&sEx2[nl][ix2];
            float2 ex1 = *(const float2*)&sEx1q[nl][ix2];
            float ey2 = sEy2[nl][iyl];
            float ey1 = sEy1q[nl][iyl];
            accv[0] += ey2 * ex2.x;  accm[0] += ey1 * ex1.x;
            accv[1] += ey2 * ex2.y;  accm[1] += ey1 * ex1.y;
        }
    }
#pragma unroll
    for (int q = 0; q < 2; q++) {
        int g = (iy0 + iyl) * 64 + ix2 + q;
        float v = C_V * accv[q] - C_M2 * accm[q];
        g_vraw[b*GG + g] = v;
        out_v[b*GG + g]  = fmaxf(v, 1e-6f);
    }
}

// =====================================================================
// L2: heterogeneous launch, 512 threads.
//   blocks 0..7       : top-100 selection (stable argsort(-v))
//   blocks 8..135     : T/U table reductions (16 per batch, 8 t-rows each)
//   blocks 136..4231  : m = C_M*Ey1*Ex1  (HBM-bound write)
// =====================================================================
__device__ __forceinline__ unsigned int fordu(float f)
{
    unsigned int u = __float_as_uint(f);
    return (u & 0x80000000u) ? ~u : (u | 0x80000000u);
}

union SmemL2 {
    struct { unsigned long long keys[4096]; unsigned int top[128]; } s;
    struct { float tx[32][128], ux[32][128]; float ty[32][8], uy[32][8]; } t;
    struct { float ex[64], ey[64]; } m;
};

__global__ void __launch_bounds__(512) k_sort_tab_m(const float* __restrict__ pts,
                                                    float* __restrict__ out_minds,
                                                    float* __restrict__ out_m)
{
    __shared__ SmemL2 u;
    int tid = threadIdx.x;
    int bx = blockIdx.x;

    if (bx >= 136) {
        // ---- m part ----
        int bn = bx - 136;
        float x = pts[2*bn], y = pts[2*bn + 1];
        if (tid < 64) {
            float cd = 8.0f * (float)tid + 4.0f;
            float dx = x - cd;
            u.m.ex[tid] = expf(-dx*dx * (1.0f/256.0f));
        } else if (tid < 128) {
            int j = tid - 64;
            float cd = 8.0f * (float)j + 4.0f;
            float dy = y - cd;
            u.m.ey[j] = expf(-dy*dy * (1.0f/256.0f));
        }
        __syncthreads();
        float4* mrow = (float4*)(out_m + (size_t)bn * GG);
        for (int i = tid; i < 1024; i += 512) {
            int g0 = i << 2;
            int iy = g0 >> 6, ix = g0 & 63;
            float e = C_M * u.m.ey[iy];
            mrow[i] = make_float4(e*u.m.ex[ix], e*u.m.ex[ix+1], e*u.m.ex[ix+2], e*u.m.ex[ix+3]);
        }
        return;
    }
    if (bx >= 8) {
        // ---- T/U table part: T[t][s] = sum_n Ey192[t]*Ex192[s]; U likewise ----
        int u2 = bx - 8;
        int b = u2 >> 4;
        int t00 = (u2 & 15) << 3;            // 8 t-rows per block
        int ox = (tid & 31) << 2;            // 4 s per thread
        int oyp = tid >> 5;                  // active threads: 0..3 (2 rows each)
        bool act = (tid < 128);
        float accT[2][4], accU[2][4];
#pragma unroll
        for (int r = 0; r < 2; r++)
#pragma unroll
            for (int q = 0; q < 4; q++) { accT[r][q] = 0.f; accU[r][q] = 0.f; }

        for (int c = 0; c < 16; c++) {
            int n0 = c << 5;
            __syncthreads();
            const float4* px = (const float4*)&g_Ex192[b][n0][0];
            const float4* pu = (const float4*)&g_Ex128[b][n0][0];
            for (int idx = tid; idx < 1024; idx += 512) {
                ((float4*)u.t.tx)[idx] = px[idx];
                ((float4*)u.t.ux)[idx] = pu[idx];
            }
            {
                int idx = tid;
                if (idx < 256) {
                    int nl = idx >> 3, yy = idx & 7;
                    u.t.ty[nl][yy] = g_Ey192[b][n0 + nl][t00 + yy];
                    u.t.uy[nl][yy] = g_Ey128[b][n0 + nl][t00 + yy];
                }
            }
            __syncthreads();
            if (act) {
#pragma unroll 4
                for (int nl = 0; nl < 32; nl++) {
                    float4 tx = *(const float4*)&u.t.tx[nl][ox];
                    float4 ux = *(const float4*)&u.t.ux[nl][ox];
                    float ty0 = u.t.ty[nl][2*oyp], ty1 = u.t.ty[nl][2*oyp+1];
                    float uy0 = u.t.uy[nl][2*oyp], uy1 = u.t.uy[nl][2*oyp+1];
                    accT[0][0] += ty0*tx.x; accT[0][1] += ty0*tx.y; accT[0][2] += ty0*tx.z; accT[0][3] += ty0*tx.w;
                    accT[1][0] += ty1*tx.x; accT[1][1] += ty1*tx.y; accT[1][2] += ty1*tx.z; accT[1][3] += ty1*tx.w;
                    accU[0][0] += uy0*ux.x; accU[0][1] += uy0*ux.y; accU[0][2] += uy0*ux.z; accU[0][3] += uy0*ux.w;
                    accU[1][0] += uy1*ux.x; accU[1][1] += uy1*ux.y; accU[1][2] += uy1*ux.z; accU[1][3] += uy1*ux.w;
                }
            }
        }
        if (act) {
#pragma unroll
            for (int r = 0; r < 2; r++) {
                int t = t00 + 2*oyp + r;
                *(float4*)&g_T[b][t][ox] = make_float4(accT[r][0], accT[r][1], accT[r][2], accT[r][3]);
                *(float4*)&g_U[b][t][ox] = make_float4(accU[r][0], accU[r][1], accU[r][2], accU[r][3]);
            }
        }
        return;
    }
    // ---- sort part ----
    int b = bx;
    for (int i = tid; i < 4096; i += 512) {
        float v = g_vraw[b*GG + i];
        u.s.keys[i] = ((unsigned long long)(~fordu(v)) << 32) | (unsigned int)i;
    }
    for (int k = 2; k <= 4096; k <<= 1)
        for (int j = k >> 1; j > 0; j >>= 1) {
            __syncthreads();
            for (int i = tid; i < 4096; i += 512) {
                int ixj = i ^ j;
                if (ixj > i) {
                    unsigned long long a = u.s.keys[i], c = u.s.keys[ixj];
                    bool up = ((i & k) == 0);
                    if ((a > c) == up) { u.s.keys[i] = c; u.s.keys[ixj] = a; }
                }
            }
        }
    __syncthreads();
    if (tid < 128)
        u.s.top[tid] = (tid < 100) ? (unsigned int)(u.s.keys[tid] & 0xFFFFFFFFu) : 0xFFFFFFFFu;
    for (int k = 2; k <= 128; k <<= 1)
        for (int j = k >> 1; j > 0; j >>= 1) {
            __syncthreads();
            if (tid < 128) {
                int i = tid, ixj = i ^ j;
                if (ixj > i) {
                    unsigned int a = u.s.top[i], c = u.s.top[ixj];
                    bool up = ((i & k) == 0);
                    if ((a > c) == up) { u.s.top[i] = c; u.s.top[ixj] = a; }
                }
            }
        }
    __syncthreads();
    if (tid < 100) {
        int mind = (int)u.s.top[tid];
        g_minds[b*MMM + tid] = mind;
        out_minds[b*MMM + tid] = (float)mind;
        float vr = g_vraw[b*GG + mind];
        g_vM[b*MMM + tid] = fmaxf(vr, 1e-6f) + 1e-10f;
    }
}

// =====================================================================
// L3 (fused): A assembly from tables (per-element, symmetric formula —
// identical values to the standalone k_A) + R12's proven smem fp32
// Gauss-Jordan with partial pivoting, now at 1024 threads.
//   E = A + diag(vM);  Bm = diag(1/vM) - inv(E)  (column-permuted gather).
// All phases are element-parallel: values independent of thread mapping.
// =====================================================================
__global__ void __launch_bounds__(1024, 1) k_Ainv(float* __restrict__ out_A,
                                                  float* __restrict__ out_Bm)
{
    __shared__ float sA[100][101];
    __shared__ float rowk[104];
    __shared__ float colk[104];
    __shared__ float svm[100];
    __shared__ int six[100], siy[100];
    __shared__ int piv[100];
    __shared__ int cperm[104];
    __shared__ int s_pr;
    __shared__ float s_pinv;

    int b = blockIdx.x, tid = threadIdx.x;
    if (tid < 100) {
        svm[tid] = g_vM[b*MMM + tid];
        int mind = g_minds[b*MMM + tid];
        six[tid] = mind & 63;
        siy[tid] = mind >> 6;
    }
    __syncthreads();

    // ---- build A from tables (write out) and E = A + diag(vM) in smem ----
    for (int idx = tid; idx < 10000; idx += 1024) {
        int ii = idx / 100, jc = idx - ii*100;
        float Aij;
        if (ii == jc) {
            Aij = 1e-10f;
        } else {
            int ixi = six[ii], iyi = siy[ii];
            int ixj = six[jc], iyj = siy[jc];
            int s = ixi + ixj, tt = iyi + iyj;
            float Tv = g_T[b][tt][s];
            float Uv = g_U[b][tt][s];
            int dix = ixi - ixj, diy = iyi - iyj;
            float d2 = (float)(dix*dix + diy*diy);
            float e1 = __expf(-0.25f  * d2);
            float e2 = __expf(-0.125f * d2);
            Aij = C_M * e1 * (C_H * Tv + 512.0f) - C_M2 * e2 * Uv;
        }
        out_A[b*10000 + idx] = Aij;
        sA[ii][jc] = Aij + ((ii == jc) ? svm[ii] : 0.0f);
    }

    int jj = tid % 100;
    int rg = tid / 100;          // 0..9 active (tid < 1000)
    bool act = (tid < 1000);
    __syncthreads();

    // ---- Gauss-Jordan, 100 steps, 3 barriers/step ----
    for (int k = 0; k < 100; k++) {
        // Phase A: warp 0 pivot search on column k, rows [k,100)
        if (tid < 32) {
            float bv = -1.0f; int br = 0x7FFFFFFF;
#pragma unroll
            for (int q = 0; q < 4; q++) {
                int r = k + tid + (q << 5);
                if (r < 100) {
                    float av = fabsf(sA[r][k]);
                    if (av > bv) { bv = av; br = r; }
                }
            }
#pragma unroll
            for (int off = 16; off; off >>= 1) {
                float ov = __shfl_down_sync(0xFFFFFFFFu, bv, off);
                int   oi = __shfl_down_sync(0xFFFFFFFFu, br, off);
                if (ov > bv || (ov == bv && oi < br)) { bv = ov; br = oi; }
            }
            if (tid == 0) {
                s_pr = br; piv[k] = br;
                s_pinv = 1.0f / sA[br][k];
            }
        }
        __syncthreads();
        int pr = s_pr;
        float pinv = s_pinv;
        // Phase B: fused swap(k,pr) + scale row k + snapshots + zero col k
        if (tid < 100) {
            int c = tid;
            float told_k = sA[k][c];
            float told_p = sA[pr][c];                 // == told_k if pr==k
            float rv = (c == k) ? pinv : told_p * pinv;
            rowk[c] = rv;
            sA[k][c] = rv;
            if (pr != k) {
                if (c == k) { colk[pr] = told_k; sA[pr][k] = 0.0f; }
                else        { sA[pr][c] = told_k; }
            }
        } else if (tid >= 256 && tid < 356) {
            int r = tid - 256;
            if (r != k && r != pr) {
                colk[r] = sA[r][k];
                sA[r][k] = 0.0f;
            }
        }
        __syncthreads();
        // Phase C: eliminate (j==k yields -f*pinv via zeroed column)
        if (act) {
            float rk = rowk[jj];
#pragma unroll
            for (int t = 0; t < 10; t++) {
                int rr = rg + t*10;
                if (rr != k) sA[rr][jj] -= colk[rr] * rk;
            }
        }
        __syncthreads();
    }
    // column permutation from reversed row swaps
    if (tid == 0) {
        for (int j2 = 0; j2 < 100; j2++) cperm[j2] = j2;
        for (int k = 99; k >= 0; k--) {
            int pp = piv[k];
            int t = cperm[k]; cperm[k] = cperm[pp]; cperm[pp] = t;
        }
    }
    __syncthreads();
    // Bm = diag(1/vM) - W  (W = permuted-inverse gather)
    for (int idx = tid; idx < 10000; idx += 1024) {
        int ii = idx / 100, jc = idx - ii*100;
        float w = sA[ii][cperm[jc]];
        float d = (ii == jc) ? (1.0f / svm[ii]) : 0.0f;
        out_Bm[b*10000 + idx] = d - w;
    }
}

// =====================================================================
// launch
// =====================================================================
extern "C" void kernel_launch(void* const* d_in, const int* in_sizes, int n_in,
                              void* d_out, int out_size)
{
    const float* pts = (const float*)d_in[0];
    float* out       = (float*)d_out;
    float* out_m     = out;                                   // 8*512*4096
    float* out_v     = out_m + (size_t)NB*NP*GG;              // 8*4096
    float* out_A     = out_v + (size_t)NB*GG;                 // 8*100*100
    float* out_Bm    = out_A + (size_t)NB*MMM*MMM;            // 8*100*100
    float* out_minds = out_Bm + (size_t)NB*MMM*MMM;           // 8*100

    k_v_emid<<<64 + 512, 256>>>(pts, out_v);
    k_sort_tab_m<<<8 + 128 + NB*NP, 512>>>(pts, out_minds, out_m);
    k_Ainv<<<NB, 1024>>>(out_A, out_Bm);
}